// round 15
// baseline (speedup 1.0000x reference)
#include <cuda_runtime.h>

// RandomShiftsAug == integer gather from the replicate-padded (pad=4) image:
//   out[n,c,i,j] = x[n,c, clamp(i+sy-4,0,223), clamp(j+sx-4,0,223)]
// R15: persistent grid-stride version of the R8 body. 444 CTAs (148 SMs x 3)
// each loop over ~18 tiles -> no wave-transition/drain overhead, balanced
// tail. Per-tile: aligned LDG.128 pairs + uniform funnel select; plain
// loads/stores (all L2-policy experiments measured dead).

#define N_   128
#define C_   9
#define H_   224
#define W_   224
#define PAD_ 4
#define ROWS_ 4
#define RY_   8
#define TILES_X 7                    // H / (RY_*ROWS_)
#define NTILES  (TILES_X * N_ * C_)  // 8064
#define NCTA    444                  // 148 SMs * 3 resident CTAs

__global__ __launch_bounds__(448) void random_shift_kernel(
    const float* __restrict__ x,
    const int*   __restrict__ shift,
    float*       __restrict__ out)
{
    const int tx = threadIdx.x;
    const int j0 = tx * 4;

    for (int t = blockIdx.x; t < NTILES; t += NCTA) {
        const int bx = t % TILES_X;
        const int nc = t / TILES_X;
        const int n  = nc / C_;

        const int dx = shift[2 * n + 0] - PAD_;   // [-4,4], uniform per image
        const int dy = shift[2 * n + 1] - PAD_;

        const size_t img = (size_t)nc * (H_ * W_);
        const int i0 = bx * (RY_ * ROWS_) + threadIdx.y;

        const float* __restrict__ src[ROWS_];
        #pragma unroll
        for (int rr = 0; rr < ROWS_; rr++) {
            int si = i0 + RY_ * rr + dy;
            si = si < 0 ? 0 : (si > H_ - 1 ? H_ - 1 : si);
            src[rr] = x + img + (size_t)si * W_;
        }

        float4 v[ROWS_];

        if (tx >= 1 && tx <= 53) {
            // interior: aligned window [a, a+7] guaranteed inside the row
            const int a = j0 + (dx & ~3);   // 16B-aligned since j0 % 4 == 0
            const int r = dx & 3;           // uniform per image

            if (r == 0) {
                #pragma unroll
                for (int rr = 0; rr < ROWS_; rr++)
                    v[rr] = *(const float4*)(src[rr] + a);
            } else {
                float4 A[ROWS_], B[ROWS_];
                #pragma unroll
                for (int rr = 0; rr < ROWS_; rr++) {
                    A[rr] = *(const float4*)(src[rr] + a);
                    B[rr] = *(const float4*)(src[rr] + a + 4);
                }
                #pragma unroll
                for (int rr = 0; rr < ROWS_; rr++) {
                    float4 o;
                    if (r == 1)
                        o = make_float4(A[rr].y, A[rr].z, A[rr].w, B[rr].x);
                    else if (r == 2)
                        o = make_float4(A[rr].z, A[rr].w, B[rr].x, B[rr].y);
                    else
                        o = make_float4(A[rr].w, B[rr].x, B[rr].y, B[rr].z);
                    v[rr] = o;
                }
            }
        } else {
            // edge lanes (tx = 0, 54, 55): scalar clamped gather
            int ja = j0 + 0 + dx;
            int jb = j0 + 1 + dx;
            int jc = j0 + 2 + dx;
            int jd = j0 + 3 + dx;
            ja = ja < 0 ? 0 : (ja > W_ - 1 ? W_ - 1 : ja);
            jb = jb < 0 ? 0 : (jb > W_ - 1 ? W_ - 1 : jb);
            jc = jc < 0 ? 0 : (jc > W_ - 1 ? W_ - 1 : jc);
            jd = jd < 0 ? 0 : (jd > W_ - 1 ? W_ - 1 : jd);
            #pragma unroll
            for (int rr = 0; rr < ROWS_; rr++) {
                v[rr].x = __ldg(src[rr] + ja);
                v[rr].y = __ldg(src[rr] + jb);
                v[rr].z = __ldg(src[rr] + jc);
                v[rr].w = __ldg(src[rr] + jd);
            }
        }

        #pragma unroll
        for (int rr = 0; rr < ROWS_; rr++) {
            float4* dst = (float4*)(out + img + (size_t)(i0 + RY_ * rr) * W_ + j0);
            *dst = v[rr];
        }
    }
}

extern "C" void kernel_launch(void* const* d_in, const int* in_sizes, int n_in,
                              void* d_out, int out_size)
{
    const float* x     = (const float*)d_in[0];
    const int*   shift = (const int*)d_in[1];
    float*       out   = (float*)d_out;

    dim3 block(56, RY_);     // 448 threads
    random_shift_kernel<<<NCTA, block>>>(x, shift, out);
}

// round 16
// speedup vs baseline: 1.1156x; 1.1156x over previous
#include <cuda_runtime.h>

// RandomShiftsAug == integer gather from the replicate-padded (pad=4) image:
//   out[n,c,i,j] = x[n,c, clamp(i+sy-4,0,223), clamp(j+sx-4,0,223)]
// R16: best-of-breed. R8's aligned LDG.128 + uniform funnel-select body
// (halves LDG instructions / L1 wavefronts) on R2's geometry (224-thr
// blocks, 16128 CTAs, occ ~76-84%) which gave the best measured kernel time.
// Plain loads/stores: every L2-policy variant measured neutral-to-worse.

#define N_   128
#define C_   9
#define H_   224
#define W_   224
#define PAD_ 4
#define ROWS_ 4
#define RY_   4   // threadIdx.y extent; tile = RY_*ROWS_ = 16 rows

__global__ __launch_bounds__(224) void random_shift_kernel(
    const float* __restrict__ x,
    const int*   __restrict__ shift,
    float*       __restrict__ out)
{
    const int nc = blockIdx.y;            // n*C_ + c
    const int n  = nc / C_;

    const int dx = shift[2 * n + 0] - PAD_;   // [-4,4], uniform per image
    const int dy = shift[2 * n + 1] - PAD_;

    const int tx = threadIdx.x;
    const int j0 = tx * 4;
    const size_t img = (size_t)nc * (H_ * W_);
    const int i0 = blockIdx.x * (RY_ * ROWS_) + threadIdx.y;

    const float* __restrict__ src[ROWS_];
    #pragma unroll
    for (int rr = 0; rr < ROWS_; rr++) {
        int si = i0 + RY_ * rr + dy;
        si = si < 0 ? 0 : (si > H_ - 1 ? H_ - 1 : si);
        src[rr] = x + img + (size_t)si * W_;
    }

    float4 v[ROWS_];

    if (tx >= 1 && tx <= 53) {
        // interior: aligned window [a, a+7] guaranteed inside the row
        const int a = j0 + (dx & ~3);   // 16B-aligned since j0 % 4 == 0
        const int r = dx & 3;           // uniform per image

        if (r == 0) {
            #pragma unroll
            for (int rr = 0; rr < ROWS_; rr++)
                v[rr] = *(const float4*)(src[rr] + a);
        } else {
            float4 A[ROWS_], B[ROWS_];
            #pragma unroll
            for (int rr = 0; rr < ROWS_; rr++) {
                A[rr] = *(const float4*)(src[rr] + a);
                B[rr] = *(const float4*)(src[rr] + a + 4);
            }
            #pragma unroll
            for (int rr = 0; rr < ROWS_; rr++) {
                float4 o;
                if (r == 1)
                    o = make_float4(A[rr].y, A[rr].z, A[rr].w, B[rr].x);
                else if (r == 2)
                    o = make_float4(A[rr].z, A[rr].w, B[rr].x, B[rr].y);
                else
                    o = make_float4(A[rr].w, B[rr].x, B[rr].y, B[rr].z);
                v[rr] = o;
            }
        }
    } else {
        // edge lanes (tx = 0, 54, 55): scalar clamped gather
        int ja = j0 + 0 + dx;
        int jb = j0 + 1 + dx;
        int jc = j0 + 2 + dx;
        int jd = j0 + 3 + dx;
        ja = ja < 0 ? 0 : (ja > W_ - 1 ? W_ - 1 : ja);
        jb = jb < 0 ? 0 : (jb > W_ - 1 ? W_ - 1 : jb);
        jc = jc < 0 ? 0 : (jc > W_ - 1 ? W_ - 1 : jc);
        jd = jd < 0 ? 0 : (jd > W_ - 1 ? W_ - 1 : jd);
        #pragma unroll
        for (int rr = 0; rr < ROWS_; rr++) {
            v[rr].x = __ldg(src[rr] + ja);
            v[rr].y = __ldg(src[rr] + jb);
            v[rr].z = __ldg(src[rr] + jc);
            v[rr].w = __ldg(src[rr] + jd);
        }
    }

    #pragma unroll
    for (int rr = 0; rr < ROWS_; rr++) {
        float4* dst = (float4*)(out + img + (size_t)(i0 + RY_ * rr) * W_ + j0);
        *dst = v[rr];
    }
}

extern "C" void kernel_launch(void* const* d_in, const int* in_sizes, int n_in,
                              void* d_out, int out_size)
{
    const float* x     = (const float*)d_in[0];
    const int*   shift = (const int*)d_in[1];
    float*       out   = (float*)d_out;

    dim3 block(56, RY_);                     // 224 threads
    dim3 grid(H_ / (RY_ * ROWS_), N_ * C_);  // (14, 1152)
    random_shift_kernel<<<grid, block>>>(x, shift, out);
}